// round 8
// baseline (speedup 1.0000x reference)
#include <cuda_runtime.h>
#include <math.h>

#define BATCH 128
#define FEAT  1024
#define CLS   500
#define HID   512

#define HSPLIT 4
#define HCH    (HID / HSPLIT)    // 128

// Scratch (device globals: allocations forbidden)
__device__ float g_imgT[HID * BATCH];           // img @ W1a^T + b1, [h][b]
__device__ float g_pattr[2][512 * HID];         // attr @ W1b^T K-split partials, [c][h]
__device__ float g_part[HSPLIT][512 * BATCH];   // relscore partials [c*128+b]

// ---------- f32x2 helpers ----------
__device__ __forceinline__ float2 unpk2(unsigned long long v) {
    float2 r;
    asm("mov.b64 {%0, %1}, %2;" : "=f"(r.x), "=f"(r.y) : "l"(v));
    return r;
}
__device__ __forceinline__ void ffma2(unsigned long long& d,
                                      unsigned long long a, unsigned long long b) {
    asm("fma.rn.f32x2 %0, %1, %2, %0;" : "+l"(d) : "l"(a), "l"(b));
}

// ---------------------------------------------------------------------
// Projection GEMM. BM=32 x BN=64 x BK=32, 128 threads, micro 2m x 8n.
// A staged PRE-DUPLICATED: As2[k][mp] = (a[2mp],a[2mp],a[2mp+1],a[2mp+1])
// -> inner loop is 3x LDS.128 + 8x FFMA2 per k-step, no MOVs.
// by 0..3   : img rows, full K=1024       -> g_imgT [h][b] (+b1)
// by 4..35  : attr tiles x K-split(2)     -> g_pattr[ks] [c][h]
// ---------------------------------------------------------------------
#define BM 32
#define BN 64
#define BK 32

__global__ __launch_bounds__(128) void gemm_proj(
    const float* __restrict__ img, const float* __restrict__ attr,
    const float* __restrict__ W1, const float* __restrict__ b1)
{
    __shared__ float As2[2][BK][68];   // duplicated pairs: 64 payload + 4 pad (272B rows)
    __shared__ float Bs[2][BK][68];    // [k][n]: 64 payload + 4 pad

    const int tid = threadIdx.x;
    const int tx  = tid & 7;           // n-group: 8 n each
    const int ty  = tid >> 3;          // m-pair: 0..15
    const int n0  = blockIdx.x * BN;
    const int by  = blockIdx.y;

    const bool is_img = (by < 4);
    int row0, kbase, kiters, ks = 0;
    const float* Aop;
    if (is_img) { row0 = by * BM; kbase = 0; kiters = FEAT / BK; Aop = img; }
    else {
        const int t = by - 4;
        row0 = (t >> 1) * BM; ks = t & 1; kbase = ks * (FEAT / 2);
        kiters = (FEAT / 2) / BK; Aop = attr;
    }
    const int rowsM = is_img ? BATCH : CLS;
    const int kW    = (is_img ? 0 : FEAT) + kbase;

    // loader lanes
    const int m_a = tid & 31, kq_a = tid >> 5;   // A: (m, quad kq_a and kq_a+4)
    const int n_b = tid & 63, kh  = tid >> 6;    // B: (n, 16-float half kh)

    const float* Ap = (row0 + m_a < rowsM)
        ? &Aop[(size_t)(row0 + m_a) * FEAT + kbase + kq_a * 4] : nullptr;
    const float* Bp = &W1[(size_t)(n0 + n_b) * (2 * FEAT) + kW + kh * 16];

    const int a_sm = (m_a >> 1) * 4 + (m_a & 1) * 2;   // dup slot base in As2 row

    unsigned long long acc0[4] = {0ull, 0ull, 0ull, 0ull};
    unsigned long long acc1[4] = {0ull, 0ull, 0ull, 0ull};

    const float4 z4 = make_float4(0.f, 0.f, 0.f, 0.f);
    float4 a_pf0 = Ap ? *(const float4*)Ap        : z4;
    float4 a_pf1 = Ap ? *(const float4*)(Ap + 16) : z4;
    float4 b_pf0 = *(const float4*)(Bp + 0);
    float4 b_pf1 = *(const float4*)(Bp + 4);
    float4 b_pf2 = *(const float4*)(Bp + 8);
    float4 b_pf3 = *(const float4*)(Bp + 12);

    for (int it = 0; it < kiters; it++) {
        const int p = it & 1;
        // stage A duplicated
        {
            const float* v0 = (const float*)&a_pf0;
            const float* v1 = (const float*)&a_pf1;
            #pragma unroll
            for (int j = 0; j < 4; j++) {
                float* r0 = &As2[p][kq_a * 4 + j][a_sm];
                r0[0] = v0[j]; r0[1] = v0[j];
                float* r1 = &As2[p][(kq_a + 4) * 4 + j][a_sm];
                r1[0] = v1[j]; r1[1] = v1[j];
            }
        }
        // stage B
        {
            const float* w0 = (const float*)&b_pf0;
            const float* w1 = (const float*)&b_pf1;
            const float* w2 = (const float*)&b_pf2;
            const float* w3 = (const float*)&b_pf3;
            #pragma unroll
            for (int j = 0; j < 4; j++) {
                Bs[p][kh * 16 + 0  + j][n_b] = w0[j];
                Bs[p][kh * 16 + 4  + j][n_b] = w1[j];
                Bs[p][kh * 16 + 8  + j][n_b] = w2[j];
                Bs[p][kh * 16 + 12 + j][n_b] = w3[j];
            }
        }
        __syncthreads();

        if (it + 1 < kiters) {           // prefetch next k-slab
            const int ko = (it + 1) * BK;
            a_pf0 = Ap ? *(const float4*)(Ap + ko)      : z4;
            a_pf1 = Ap ? *(const float4*)(Ap + ko + 16) : z4;
            b_pf0 = *(const float4*)(Bp + ko + 0);
            b_pf1 = *(const float4*)(Bp + ko + 4);
            b_pf2 = *(const float4*)(Bp + ko + 8);
            b_pf3 = *(const float4*)(Bp + ko + 12);
        }

        #pragma unroll
        for (int kk = 0; kk < BK; kk++) {
            ulonglong2 ad  = *(ulonglong2*)&As2[p][kk][ty * 4];   // (a0,a0),(a1,a1)
            ulonglong2 b01 = *(ulonglong2*)&Bs[p][kk][tx * 8];
            ulonglong2 b23 = *(ulonglong2*)&Bs[p][kk][tx * 8 + 4];
            ffma2(acc0[0], ad.x, b01.x); ffma2(acc0[1], ad.x, b01.y);
            ffma2(acc0[2], ad.x, b23.x); ffma2(acc0[3], ad.x, b23.y);
            ffma2(acc1[0], ad.y, b01.x); ffma2(acc1[1], ad.y, b01.y);
            ffma2(acc1[2], ad.y, b23.x); ffma2(acc1[3], ad.y, b23.y);
        }
        __syncthreads();
    }

    const int h = n0 + tx * 8;
    if (is_img) {
        const int b = row0 + ty * 2;
        #pragma unroll
        for (int np = 0; np < 4; np++) {
            const float bb0 = b1[h + 2 * np], bb1 = b1[h + 2 * np + 1];
            float2 v0 = unpk2(acc0[np]);
            float2 v1 = unpk2(acc1[np]);
            g_imgT[(h + 2 * np)     * BATCH + b]     = v0.x + bb0;
            g_imgT[(h + 2 * np + 1) * BATCH + b]     = v0.y + bb1;
            g_imgT[(h + 2 * np)     * BATCH + b + 1] = v1.x + bb0;
            g_imgT[(h + 2 * np + 1) * BATCH + b + 1] = v1.y + bb1;
        }
    } else {
        const int c = row0 + ty * 2;           // padded to 512 rows: no guard
        float* P = g_pattr[ks];
        ulonglong2 u;
        u.x = acc0[0]; u.y = acc0[1]; *(ulonglong2*)&P[(size_t)c * HID + h]           = u;
        u.x = acc0[2]; u.y = acc0[3]; *(ulonglong2*)&P[(size_t)c * HID + h + 4]       = u;
        u.x = acc1[0]; u.y = acc1[1]; *(ulonglong2*)&P[(size_t)(c + 1) * HID + h]     = u;
        u.x = acc1[2]; u.y = acc1[3]; *(ulonglong2*)&P[(size_t)(c + 1) * HID + h + 4] = u;
    }
}

// ---------------------------------------------------------------------
// part[hs][c,b] = sum_{h chunk} relu(imgT[h,b] + attr[c,h]) * W2[h]
// attr K-split partials folded during the smem fill.
// Grid: (63 c-tiles of 8, 4 h-splits), 128 threads = one per b.
// ---------------------------------------------------------------------
#define CT 8

__global__ __launch_bounds__(128) void relscore(const float* __restrict__ W2)
{
    __shared__ float attr8[HCH][CT];   // 32B rows -> aligned float4 broadcast
    __shared__ float w2s[HCH];

    const int b  = threadIdx.x;
    const int c0 = blockIdx.x * CT;
    const int h0 = blockIdx.y * HCH;

    #pragma unroll
    for (int i = 0; i < CT; i++) {
        const int t  = i * 128 + b;
        const int cc = t >> 7, hh = t & 127;
        const int c  = c0 + cc;
        attr8[hh][cc] = (c < CLS)
            ? g_pattr[0][(size_t)c * HID + h0 + hh] + g_pattr[1][(size_t)c * HID + h0 + hh]
            : 0.f;
    }
    w2s[b] = W2[h0 + b];
    __syncthreads();

    float acc[CT];
    #pragma unroll
    for (int i = 0; i < CT; i++) acc[i] = 0.f;

    const float* ip = g_imgT + (size_t)h0 * BATCH + b;

    #pragma unroll 8
    for (int hh = 0; hh < HCH; hh++) {
        const float iv = ip[(size_t)hh * BATCH];   // coalesced over threads
        const float w  = w2s[hh];
        float4 a0 = *(float4*)&attr8[hh][0];       // warp-broadcast
        float4 a1 = *(float4*)&attr8[hh][4];
        acc[0] += fmaxf(iv + a0.x, 0.f) * w;
        acc[1] += fmaxf(iv + a0.y, 0.f) * w;
        acc[2] += fmaxf(iv + a0.z, 0.f) * w;
        acc[3] += fmaxf(iv + a0.w, 0.f) * w;
        acc[4] += fmaxf(iv + a1.x, 0.f) * w;
        acc[5] += fmaxf(iv + a1.y, 0.f) * w;
        acc[6] += fmaxf(iv + a1.z, 0.f) * w;
        acc[7] += fmaxf(iv + a1.w, 0.f) * w;
    }

    float* part = g_part[blockIdx.y];
    #pragma unroll
    for (int cc = 0; cc < CT; cc++) {
        const int c = c0 + cc;
        if (c < CLS) part[c * BATCH + b] = acc[cc];   // coalesced over b
    }
}

// ---------------------------------------------------------------------
// out[b, c0..c0+3] = sigmoid(sum of 4 partials + b2), float4 store.
// ---------------------------------------------------------------------
__global__ __launch_bounds__(128) void finalize(float* __restrict__ out,
                                                const float* __restrict__ b2)
{
    const int b  = threadIdx.x;
    const int c0 = blockIdx.x * 4;
    const float bias = b2[0];

    float4 r;
    float* rv = (float*)&r;
    #pragma unroll
    for (int j = 0; j < 4; j++) {
        const int idx = (c0 + j) * BATCH + b;
        float s = bias;
        #pragma unroll
        for (int k = 0; k < HSPLIT; k++) s += g_part[k][idx];   // coalesced
        rv[j] = 1.f / (1.f + __expf(-s));
    }
    *(float4*)&out[(size_t)b * CLS + c0] = r;   // aligned: CLS%4==0, c0%4==0
}

// ---------------------------------------------------------------------
extern "C" void kernel_launch(void* const* d_in, const int* in_sizes, int n_in,
                              void* d_out, int out_size)
{
    const float* img  = (const float*)d_in[0];
    const float* attr = (const float*)d_in[1];
    const float* W1   = (const float*)d_in[2];
    const float* b1   = (const float*)d_in[3];
    const float* W2   = (const float*)d_in[4];
    const float* b2   = (const float*)d_in[5];
    float* out = (float*)d_out;

    gemm_proj<<<dim3(HID / BN, 36), 128>>>(img, attr, W1, b1);   // 288 blocks
    relscore<<<dim3((CLS + CT - 1) / CT, HSPLIT), 128>>>(W2);    // 252 blocks
    finalize<<<CLS / 4, 128>>>(out, b2);                         // 125 blocks
}

// round 14
// speedup vs baseline: 1.7004x; 1.7004x over previous
#include <cuda_runtime.h>
#include <cuda_bf16.h>
#include <math.h>
#include <cstdint>

#define BATCH 128
#define FEAT  1024
#define CLS   500
#define HID   512

#define HSPLIT 4
#define HCH    (HID / HSPLIT)    // 128

#define AROWS 640                // 128 img + 500 attr + pad
#define KP    3072               // augmented K: A=[hi,lo,hi], B=[hi,hi,lo]

// ---------------- device scratch ----------------
__device__ __align__(16) unsigned short g_A[AROWS * KP];     // bf16 bits
__device__ __align__(16) unsigned short g_B[2][HID * KP];    // [W1 half][n][k']
__device__ float g_imgT[HID * BATCH];                        // [h][b], b1 folded
__device__ float g_attr[512 * HID];                          // [c][h]
__device__ float g_part[HSPLIT][512 * BATCH];                // relscore partials

// ---------------- warp-MMA primitives (baseline ISA, sm_80+) ----------------
__device__ __forceinline__ uint32_t smem_u32(const void* p) {
    uint32_t a;
    asm("{ .reg .u64 t; cvta.to.shared.u64 t, %1; cvt.u32.u64 %0, t; }" : "=r"(a) : "l"(p));
    return a;
}
__device__ __forceinline__ void ldsm_x4(uint32_t* r, uint32_t addr) {
    asm volatile("ldmatrix.sync.aligned.m8n8.x4.shared.b16 {%0,%1,%2,%3}, [%4];"
                 : "=r"(r[0]), "=r"(r[1]), "=r"(r[2]), "=r"(r[3]) : "r"(addr));
}
__device__ __forceinline__ void mma_bf16(float* c, const uint32_t* a, const uint32_t* b) {
    asm volatile("mma.sync.aligned.m16n8k16.row.col.f32.bf16.bf16.f32 "
        "{%0,%1,%2,%3}, {%4,%5,%6,%7}, {%8,%9}, {%0,%1,%2,%3};"
        : "+f"(c[0]), "+f"(c[1]), "+f"(c[2]), "+f"(c[3])
        : "r"(a[0]), "r"(a[1]), "r"(a[2]), "r"(a[3]), "r"(b[0]), "r"(b[1]));
}

// ---------------------------------------------------------------------
// fp32 -> bf16 hi/lo augmented operands.
// ---------------------------------------------------------------------
__device__ __forceinline__ void split4(float4 v, uint2& hi, uint2& lo) {
    const float* f = (const float*)&v;
    unsigned short h[4], l[4];
    #pragma unroll
    for (int i = 0; i < 4; i++) {
        __nv_bfloat16 hb = __float2bfloat16(f[i]);
        h[i] = __bfloat16_as_ushort(hb);
        l[i] = __bfloat16_as_ushort(__float2bfloat16(f[i] - __bfloat162float(hb)));
    }
    hi.x = (uint32_t)h[0] | ((uint32_t)h[1] << 16);
    hi.y = (uint32_t)h[2] | ((uint32_t)h[3] << 16);
    lo.x = (uint32_t)l[0] | ((uint32_t)l[1] << 16);
    lo.y = (uint32_t)l[2] | ((uint32_t)l[3] << 16);
}

#define CONV_A (AROWS * 256)
#define CONV_B (2 * HID * 256)

__global__ __launch_bounds__(256) void convert_bf16(
    const float* __restrict__ img, const float* __restrict__ attr,
    const float* __restrict__ W1)
{
    const int idx = blockIdx.x * 256 + threadIdx.x;
    if (idx < CONV_A) {
        const int r = idx >> 8, k = (idx & 255) * 4;
        float4 v = make_float4(0.f, 0.f, 0.f, 0.f);
        if (r < 128)      v = *(const float4*)&img[(size_t)r * FEAT + k];
        else if (r < 628) v = *(const float4*)&attr[(size_t)(r - 128) * FEAT + k];
        uint2 hi, lo; split4(v, hi, lo);
        *(uint2*)&g_A[(size_t)r * KP + k]        = hi;
        *(uint2*)&g_A[(size_t)r * KP + 1024 + k] = lo;
        *(uint2*)&g_A[(size_t)r * KP + 2048 + k] = hi;
    } else if (idx < CONV_A + CONV_B) {
        int j = idx - CONV_A;
        const int half = j >= HID * 256; if (half) j -= HID * 256;
        const int n = j >> 8, k = (j & 255) * 4;
        float4 v = *(const float4*)&W1[(size_t)n * (2 * FEAT) + half * FEAT + k];
        uint2 hi, lo; split4(v, hi, lo);
        unsigned short* Bp = g_B[half];
        *(uint2*)&Bp[(size_t)n * KP + k]        = hi;
        *(uint2*)&Bp[(size_t)n * KP + 1024 + k] = hi;
        *(uint2*)&Bp[(size_t)n * KP + 2048 + k] = lo;
    }
}

// ---------------------------------------------------------------------
// HMMA GEMM: D[64m x 32n] per block, 128 threads (2x2 warps, warp 32m x 16n).
// by 0..1: img rows (-> g_imgT [h][b] + b1); by 2..9: attr rows (-> g_attr [c][h]).
// Double-buffered smem, register-prefetch LDG, 48 K-slabs of 64.
// B smem is [n][k] row-major -> NON-trans ldmatrix yields the col-major
// B fragment directly (lane: n = lane>>2, k = (lane%4)*2).  (.trans was the R12 bug)
// ---------------------------------------------------------------------
#define BLKM 64
#define BLKN 32
#define PADK 72          // bf16/row -> 144B row stride (16B-mult, conflict-free ldsm)
#define NSLAB (KP / 64)  // 48

__global__ __launch_bounds__(128) void gemm_mma(const float* __restrict__ b1)
{
    __shared__ __align__(16) unsigned short As[2][BLKM][PADK];
    __shared__ __align__(16) unsigned short Bs[2][BLKN][PADK];

    const int tid  = threadIdx.x;
    const int lane = tid & 31;
    const int warp = tid >> 5;
    const int wm   = warp & 1;        // warp m (2)
    const int wn   = warp >> 1;       // warp n (2)
    const int by   = blockIdx.y;      // m block (10)
    const int bx   = blockIdx.x;      // n block (16)
    const bool is_img = (by < 2);

    const unsigned short* Aq = g_A + (size_t)(by * BLKM) * KP;
    const unsigned short* Bq = g_B[is_img ? 0 : 1] + (size_t)(bx * BLKN) * KP;

    // ldmatrix per-lane byte offsets (within a buffer)
    const uint32_t asb = smem_u32(As);
    const uint32_t bsb = smem_u32(Bs);
    uint32_t aRow[2];
    #pragma unroll
    for (int mi = 0; mi < 2; mi++)
        aRow[mi] = (uint32_t)((wm * 32 + mi * 16 + (lane & 15)) * (PADK * 2) + (lane >> 4) * 16);
    // B x4 matrices: lanes 0-7 -> n0-7/k0, 8-15 -> n0-7/k8, 16-23 -> n8-15/k0, 24-31 -> n8-15/k8
    const int n_l = wn * 16 + (lane & 7) + ((lane >> 4) << 3);
    const uint32_t bRow = (uint32_t)(n_l * (PADK * 2) + ((lane >> 3) & 1) * 16);

    float acc[2][2][4];
    #pragma unroll
    for (int i = 0; i < 2; i++)
        #pragma unroll
        for (int j = 0; j < 2; j++)
            #pragma unroll
            for (int q = 0; q < 4; q++) acc[i][j][q] = 0.f;

    uint4 a_pf[4], b_pf[2];
    // prefetch slab 0
    #pragma unroll
    for (int i = 0; i < 4; i++) {
        const int id = i * 128 + tid;
        a_pf[i] = *(const uint4*)&Aq[(size_t)(id >> 3) * KP + (id & 7) * 8];
    }
    #pragma unroll
    for (int i = 0; i < 2; i++) {
        const int id = i * 128 + tid;
        b_pf[i] = *(const uint4*)&Bq[(size_t)(id >> 3) * KP + (id & 7) * 8];
    }

    for (int it = 0; it < NSLAB; it++) {
        const int p = it & 1;
        #pragma unroll
        for (int i = 0; i < 4; i++) {
            const int id = i * 128 + tid;
            *(uint4*)&As[p][id >> 3][(id & 7) * 8] = a_pf[i];
        }
        #pragma unroll
        for (int i = 0; i < 2; i++) {
            const int id = i * 128 + tid;
            *(uint4*)&Bs[p][id >> 3][(id & 7) * 8] = b_pf[i];
        }
        __syncthreads();

        if (it + 1 < NSLAB) {          // prefetch next slab (hidden behind MMA)
            const int k0 = (it + 1) * 64;
            #pragma unroll
            for (int i = 0; i < 4; i++) {
                const int id = i * 128 + tid;
                a_pf[i] = *(const uint4*)&Aq[(size_t)(id >> 3) * KP + k0 + (id & 7) * 8];
            }
            #pragma unroll
            for (int i = 0; i < 2; i++) {
                const int id = i * 128 + tid;
                b_pf[i] = *(const uint4*)&Bq[(size_t)(id >> 3) * KP + k0 + (id & 7) * 8];
            }
        }

        const uint32_t aBase = asb + (uint32_t)p * sizeof(As[0]);
        const uint32_t bBase = bsb + (uint32_t)p * sizeof(Bs[0]);
        #pragma unroll
        for (int ks = 0; ks < 4; ks++) {
            uint32_t af0[4], af1[4], bf[4];
            ldsm_x4(af0, aBase + aRow[0] + ks * 32);
            ldsm_x4(af1, aBase + aRow[1] + ks * 32);
            ldsm_x4(bf, bBase + bRow + ks * 32);       // NON-trans: B smem is [n][k]
            mma_bf16(acc[0][0], af0, bf + 0);
            mma_bf16(acc[0][1], af0, bf + 2);
            mma_bf16(acc[1][0], af1, bf + 0);
            mma_bf16(acc[1][1], af1, bf + 2);
        }
        __syncthreads();
    }

    // ---- writeout ----
    const int g   = lane >> 2;          // row group 0..7
    const int tc  = (lane & 3) * 2;     // col pair
    #pragma unroll
    for (int mi = 0; mi < 2; mi++) {
        #pragma unroll
        for (int half = 0; half < 2; half++) {
            const int row = by * BLKM + wm * 32 + mi * 16 + g + half * 8;
            #pragma unroll
            for (int nj = 0; nj < 2; nj++) {
                const int h = bx * BLKN + wn * 16 + nj * 8 + tc;
                const float v0 = acc[mi][nj][half * 2 + 0];
                const float v1 = acc[mi][nj][half * 2 + 1];
                if (is_img) {
                    g_imgT[(h + 0) * BATCH + row] = v0 + __ldg(&b1[h]);
                    g_imgT[(h + 1) * BATCH + row] = v1 + __ldg(&b1[h + 1]);
                } else {
                    const int c = row - 128;
                    g_attr[(size_t)c * HID + h]     = v0;   // c <= 511, buffer padded
                    g_attr[(size_t)c * HID + h + 1] = v1;
                }
            }
        }
    }
}

// ---------------------------------------------------------------------
// part[hs][c,b] = sum_{h chunk} relu(imgT[h,b] + attr[c,h]) * W2[h]
// ---------------------------------------------------------------------
#define CT 8

__global__ __launch_bounds__(128) void relscore(const float* __restrict__ W2)
{
    __shared__ float attr8[HCH][CT];
    __shared__ float w2s[HCH];

    const int b  = threadIdx.x;
    const int c0 = blockIdx.x * CT;
    const int h0 = blockIdx.y * HCH;

    #pragma unroll
    for (int i = 0; i < CT; i++) {
        const int t  = i * 128 + b;
        const int cc = t >> 7, hh = t & 127;
        const int c  = c0 + cc;
        attr8[hh][cc] = (c < CLS) ? g_attr[(size_t)c * HID + h0 + hh] : 0.f;
    }
    w2s[b] = W2[h0 + b];
    __syncthreads();

    float acc[CT];
    #pragma unroll
    for (int i = 0; i < CT; i++) acc[i] = 0.f;

    const float* ip = g_imgT + (size_t)h0 * BATCH + b;

    #pragma unroll 8
    for (int hh = 0; hh < HCH; hh++) {
        const float iv = ip[(size_t)hh * BATCH];
        const float w  = w2s[hh];
        float4 a0 = *(float4*)&attr8[hh][0];
        float4 a1 = *(float4*)&attr8[hh][4];
        acc[0] += fmaxf(iv + a0.x, 0.f) * w;
        acc[1] += fmaxf(iv + a0.y, 0.f) * w;
        acc[2] += fmaxf(iv + a0.z, 0.f) * w;
        acc[3] += fmaxf(iv + a0.w, 0.f) * w;
        acc[4] += fmaxf(iv + a1.x, 0.f) * w;
        acc[5] += fmaxf(iv + a1.y, 0.f) * w;
        acc[6] += fmaxf(iv + a1.z, 0.f) * w;
        acc[7] += fmaxf(iv + a1.w, 0.f) * w;
    }

    float* part = g_part[blockIdx.y];
    #pragma unroll
    for (int cc = 0; cc < CT; cc++) {
        const int c = c0 + cc;
        if (c < CLS) part[c * BATCH + b] = acc[cc];
    }
}

__global__ __launch_bounds__(128) void finalize(float* __restrict__ out,
                                                const float* __restrict__ b2)
{
    const int b  = threadIdx.x;
    const int c0 = blockIdx.x * 4;
    const float bias = b2[0];

    float4 r;
    float* rv = (float*)&r;
    #pragma unroll
    for (int j = 0; j < 4; j++) {
        const int idx = (c0 + j) * BATCH + b;
        float s = bias;
        #pragma unroll
        for (int k = 0; k < HSPLIT; k++) s += g_part[k][idx];
        rv[j] = 1.f / (1.f + __expf(-s));
    }
    *(float4*)&out[(size_t)b * CLS + c0] = r;
}

// ---------------------------------------------------------------------
extern "C" void kernel_launch(void* const* d_in, const int* in_sizes, int n_in,
                              void* d_out, int out_size)
{
    const float* img  = (const float*)d_in[0];
    const float* attr = (const float*)d_in[1];
    const float* W1   = (const float*)d_in[2];
    const float* b1   = (const float*)d_in[3];
    const float* W2   = (const float*)d_in[4];
    const float* b2   = (const float*)d_in[5];
    float* out = (float*)d_out;

    convert_bf16<<<(CONV_A + CONV_B + 255) / 256, 256>>>(img, attr, W1);
    gemm_mma<<<dim3(HID / BLKN, AROWS / BLKM), 128>>>(b1);   // 16 x 10 = 160 blocks
    relscore<<<dim3((CLS + CT - 1) / CT, HSPLIT), 128>>>(W2);
    finalize<<<CLS / 4, 128>>>(out, b2);
}